// round 1
// baseline (speedup 1.0000x reference)
#include <cuda_runtime.h>
#include <cstdint>

#define NN 40000
#define NE 640000
#define H  128
#define FEIN 16
#define NG 256

// ---------------- device scratch (allocation-free rule: __device__ globals) ----
__device__ float g_hbuf[2][(size_t)NN * H];
__device__ float g_Abuf[2][(size_t)NN * H];
__device__ float g_Bbuf[2][(size_t)NN * H];
__device__ float g_X[(size_t)NN * H];
__device__ float g_AdjX[(size_t)NN * H];
__device__ float g_T1[(size_t)NN * H];
__device__ float g_Se0[(size_t)NN * H];
__device__ float g_Seraw[(size_t)NN * FEIN];
__device__ float g_Cbuf[2][H * H];
__device__ float g_CW[H * H];
__device__ float g_bbuf[2][H];
__device__ float g_bW[H];
__device__ float g_degf[NN];
__device__ int   g_deg[NN];
__device__ int   g_cnt[NN];
__device__ int   g_rowptr[NN + 1];
__device__ int   g_col[NE];
__device__ int   g_scantmp[NN];
__device__ int   g_bsums[64];

// ---------------- GEMM: out[M,128] = sum_p A_p@W_p  (+deg-scaling, bias, addmat)
// out[i][j] = s_acc(i) * (sum_p (A_p@W_p)[i][j]) + s_b(i)*bias[j] + addmat[i][j]
// where s_acc(i) = deg[i] if scale_acc else 1, s_b likewise.
// Tiles: 64 rows x 128 cols per block, 256 threads, packed fma.rn.f32x2.
__global__ __launch_bounds__(256) void gemm_multi(
    float* __restrict__ out, int M,
    const float* __restrict__ A0, const float* __restrict__ W0, int K0,
    const float* __restrict__ A1, const float* __restrict__ W1, int K1,
    const float* __restrict__ A2, const float* __restrict__ W2, int K2,
    const float* __restrict__ addmat, const float* __restrict__ bias,
    int scale_acc, int scale_bias)
{
    __shared__ float As[16 * 64];    // transposed A tile: As[kk][row]
    __shared__ float Ws[16 * H];     // Ws[kk][col]
    const int t  = threadIdx.x;
    const int r  = t >> 5;           // 0..7 : row group (8 rows each)
    const int c  = t & 31;           // 0..31: col group (4 cols each)
    const int m0 = blockIdx.x * 64;

    unsigned long long acc[4][4];    // [rowpair][col], each packs 2 fp32 (rows)
    #pragma unroll
    for (int i = 0; i < 4; i++)
        #pragma unroll
        for (int j = 0; j < 4; j++) acc[i][j] = 0ULL;

    const float* Ap[3] = {A0, A1, A2};
    const float* Wp[3] = {W0, W1, W2};
    int Kp[3] = {K0, K1, K2};

    for (int p = 0; p < 3; p++) {
        const float* A = Ap[p];
        if (!A) continue;
        const float* W = Wp[p];
        const int K = Kp[p];
        for (int kt = 0; kt < K; kt += 16) {
            // load A tile (64 rows x 16 k) transposed into As[kk][row]
            {
                int row = t >> 2, q = t & 3;
                float4 v = *(const float4*)(A + (size_t)(m0 + row) * K + kt + q * 4);
                As[(q * 4 + 0) * 64 + row] = v.x;
                As[(q * 4 + 1) * 64 + row] = v.y;
                As[(q * 4 + 2) * 64 + row] = v.z;
                As[(q * 4 + 3) * 64 + row] = v.w;
            }
            // load W tile (16 k x 128 cols)
            {
                int row = t >> 5, c4 = t & 31;
                *(float4*)&Ws[row * H + c4 * 4] =
                    *(const float4*)(W + (size_t)(kt + row) * H + c4 * 4);
                *(float4*)&Ws[(row + 8) * H + c4 * 4] =
                    *(const float4*)(W + (size_t)(kt + row + 8) * H + c4 * 4);
            }
            __syncthreads();
            #pragma unroll
            for (int kk = 0; kk < 16; kk++) {
                float4 wq = *(const float4*)&Ws[kk * H + c * 4];
                unsigned long long w2[4];
                asm("mov.b64 %0,{%1,%1};" : "=l"(w2[0]) : "f"(wq.x));
                asm("mov.b64 %0,{%1,%1};" : "=l"(w2[1]) : "f"(wq.y));
                asm("mov.b64 %0,{%1,%1};" : "=l"(w2[2]) : "f"(wq.z));
                asm("mov.b64 %0,{%1,%1};" : "=l"(w2[3]) : "f"(wq.w));
                #pragma unroll
                for (int rp = 0; rp < 4; rp++) {
                    unsigned long long a2 =
                        *(const unsigned long long*)&As[kk * 64 + r * 8 + rp * 2];
                    asm("fma.rn.f32x2 %0,%1,%2,%0;" : "+l"(acc[rp][0]) : "l"(a2), "l"(w2[0]));
                    asm("fma.rn.f32x2 %0,%1,%2,%0;" : "+l"(acc[rp][1]) : "l"(a2), "l"(w2[1]));
                    asm("fma.rn.f32x2 %0,%1,%2,%0;" : "+l"(acc[rp][2]) : "l"(a2), "l"(w2[2]));
                    asm("fma.rn.f32x2 %0,%1,%2,%0;" : "+l"(acc[rp][3]) : "l"(a2), "l"(w2[3]));
                }
            }
            __syncthreads();
        }
    }

    // epilogue
    float4 bb = make_float4(0.f, 0.f, 0.f, 0.f);
    if (bias) bb = *(const float4*)&bias[c * 4];
    #pragma unroll
    for (int rp = 0; rp < 4; rp++) {
        float lo[4], hi[4];
        #pragma unroll
        for (int x = 0; x < 4; x++)
            asm("mov.b64 {%0,%1},%2;" : "=f"(lo[x]), "=f"(hi[x]) : "l"(acc[rp][x]));
        #pragma unroll
        for (int half = 0; half < 2; half++) {
            int row = m0 + r * 8 + rp * 2 + half;
            float4 v;
            v.x = half ? hi[0] : lo[0];
            v.y = half ? hi[1] : lo[1];
            v.z = half ? hi[2] : lo[2];
            v.w = half ? hi[3] : lo[3];
            float d = 1.f;
            if (scale_acc | scale_bias) d = g_degf[row];
            if (scale_acc) { v.x *= d; v.y *= d; v.z *= d; v.w *= d; }
            if (bias) {
                float s = scale_bias ? d : 1.f;
                v.x += bb.x * s; v.y += bb.y * s; v.z += bb.z * s; v.w += bb.w * s;
            }
            if (addmat) {
                float4 am = *(const float4*)&addmat[(size_t)row * H + c * 4];
                v.x += am.x; v.y += am.y; v.z += am.z; v.w += am.w;
            }
            *(float4*)&out[(size_t)row * H + c * 4] = v;
        }
    }
}

// ---------------- small dense ops -------------------------------------------
__global__ void small_mm(const float* __restrict__ A, const float* __restrict__ W,
                         float* __restrict__ out) {
    __shared__ float as[H];
    int row = blockIdx.x, j = threadIdx.x;
    as[j] = A[row * H + j];
    __syncthreads();
    float acc = 0.f;
    #pragma unroll 8
    for (int k = 0; k < H; k++) acc += as[k] * W[k * H + j];
    out[row * H + j] = acc;
}

__global__ void vecmat(const float* __restrict__ v, const float* __restrict__ W,
                       const float* __restrict__ addb, float* __restrict__ out) {
    __shared__ float vs[H];
    int j = threadIdx.x;
    vs[j] = v[j];
    __syncthreads();
    float acc = addb[j];
    #pragma unroll 8
    for (int k = 0; k < H; k++) acc += vs[k] * W[k * H + j];
    out[j] = acc;
}

// ---------------- edge preprocessing -----------------------------------------
// deg[v] and S_eraw[v][:] = sum of raw edge features over edges into v.
__global__ void edge_pre(const float* __restrict__ eraw, const int* __restrict__ rec) {
    int i = blockIdx.x * blockDim.x + threadIdx.x;
    if (i >= NE) return;
    int rcv = rec[i];
    atomicAdd(&g_deg[rcv], 1);
    const float4* ep = (const float4*)(eraw + (size_t)i * FEIN);
    float* dst = g_Seraw + (size_t)rcv * FEIN;
    #pragma unroll
    for (int q = 0; q < 4; q++) {
        float4 v = ep[q];
        atomicAdd(dst + q * 4 + 0, v.x);
        atomicAdd(dst + q * 4 + 1, v.y);
        atomicAdd(dst + q * 4 + 2, v.z);
        atomicAdd(dst + q * 4 + 3, v.w);
    }
}

#define SCB 1024
__global__ void scan1() {
    __shared__ int sm[SCB];
    int i = blockIdx.x * SCB + threadIdx.x;
    int v = (i < NN) ? g_deg[i] : 0;
    sm[threadIdx.x] = v;
    __syncthreads();
    for (int off = 1; off < SCB; off <<= 1) {
        int tval = 0;
        if ((int)threadIdx.x >= off) tval = sm[threadIdx.x - off];
        __syncthreads();
        if ((int)threadIdx.x >= off) sm[threadIdx.x] += tval;
        __syncthreads();
    }
    if (i < NN) g_scantmp[i] = sm[threadIdx.x];
    if (threadIdx.x == SCB - 1) g_bsums[blockIdx.x] = sm[SCB - 1];
}
__global__ void scan2(int nb) {
    if (threadIdx.x == 0) {
        int run = 0;
        for (int b = 0; b < nb; b++) { int t = g_bsums[b]; g_bsums[b] = run; run += t; }
    }
}
__global__ void scan3() {
    int i = blockIdx.x * SCB + threadIdx.x;
    if (i < NN) g_rowptr[i] = g_bsums[blockIdx.x] + g_scantmp[i] - g_deg[i];
    if (i == 0) g_rowptr[NN] = NE;
}
__global__ void deg2float() {
    int i = blockIdx.x * blockDim.x + threadIdx.x;
    if (i < NN) g_degf[i] = (float)g_deg[i];
}
__global__ void csr_fill(const int* __restrict__ send, const int* __restrict__ rec) {
    int i = blockIdx.x * blockDim.x + threadIdx.x;
    if (i >= NE) return;
    int rcv = rec[i];
    int pos = g_rowptr[rcv] + atomicAdd(&g_cnt[rcv], 1);
    g_col[pos] = send[i];
}

// ---------------- sparse Adj: out[v] = sum_{e: rec=v} X[send(e)] -------------
__global__ void adj_gather(const float* __restrict__ X, float* __restrict__ outm) {
    int node = blockIdx.x * 2 + (threadIdx.x >> 7);
    int j = threadIdx.x & 127;
    int b = g_rowptr[node], e = g_rowptr[node + 1];
    float acc = 0.f;
    for (int idx = b; idx < e; idx++) {
        int s = __ldg(&g_col[idx]);
        acc += __ldg(&X[(size_t)s * H + j]);
    }
    outm[(size_t)node * H + j] = acc;
}

// ---------------- global add pool --------------------------------------------
__global__ void pool_kernel(const float* __restrict__ hfin, const int* __restrict__ batch,
                            float* __restrict__ out) {
    int i = blockIdx.x * blockDim.x + threadIdx.x;
    if (i >= NN * 32) return;
    int v = i >> 5, q = i & 31;
    float4 val = *(const float4*)&hfin[(size_t)v * H + q * 4];
    int g = batch[v];
    float* o = out + (size_t)g * H + q * 4;
    atomicAdd(o + 0, val.x);
    atomicAdd(o + 1, val.y);
    atomicAdd(o + 2, val.z);
    atomicAdd(o + 3, val.w);
}

// ---------------- host --------------------------------------------------------
static inline void launch_gemm(float* out, int M,
                               const float* A0, const float* W0, int K0,
                               const float* A1, const float* W1, int K1,
                               const float* addmat, const float* bias,
                               int sa, int sb) {
    gemm_multi<<<M / 64, 256>>>(out, M, A0, W0, K0, A1, W1, K1,
                                nullptr, nullptr, 0, addmat, bias, sa, sb);
}

extern "C" void kernel_launch(void* const* d_in, const int* in_sizes, int n_in,
                              void* d_out, int out_size) {
    const float* h_in     = (const float*)d_in[0];
    const float* e_raw    = (const float*)d_in[1];
    const int*   eidx     = (const int*)d_in[2];
    const int*   batch    = (const int*)d_in[3];
    const float* W_embed  = (const float*)d_in[4];
    const float* b_embed  = (const float*)d_in[5];
    const float* W_eembed = (const float*)d_in[6];
    const float* b_eembed = (const float*)d_in[7];
    const float* Wm       = (const float*)d_in[8];
    const float* bm       = (const float*)d_in[9];
    const float* Wh       = (const float*)d_in[10];
    const float* bh       = (const float*)d_in[11];
    const float* We       = (const float*)d_in[12];
    const float* be       = (const float*)d_in[13];
    float* out = (float*)d_out;
    const int* send = eidx;
    const int* rec  = eidx + NE;

    void* tp;
    cudaGetSymbolAddress(&tp, g_hbuf);  float* ph    = (float*)tp;
    cudaGetSymbolAddress(&tp, g_Abuf);  float* pA    = (float*)tp;
    cudaGetSymbolAddress(&tp, g_Bbuf);  float* pB    = (float*)tp;
    cudaGetSymbolAddress(&tp, g_X);     float* pX    = (float*)tp;
    cudaGetSymbolAddress(&tp, g_AdjX);  float* pAdj  = (float*)tp;
    cudaGetSymbolAddress(&tp, g_T1);    float* pT1   = (float*)tp;
    cudaGetSymbolAddress(&tp, g_Se0);   float* pSe0  = (float*)tp;
    cudaGetSymbolAddress(&tp, g_Seraw); float* pSeraw= (float*)tp;
    cudaGetSymbolAddress(&tp, g_Cbuf);  float* pC    = (float*)tp;
    cudaGetSymbolAddress(&tp, g_CW);    float* pCW   = (float*)tp;
    cudaGetSymbolAddress(&tp, g_bbuf);  float* pbv   = (float*)tp;
    cudaGetSymbolAddress(&tp, g_bW);    float* pbW   = (float*)tp;
    cudaGetSymbolAddress(&tp, g_deg);   int*   pdeg  = (int*)tp;
    cudaGetSymbolAddress(&tp, g_cnt);   int*   pcnt  = (int*)tp;

    cudaMemsetAsync(pdeg, 0, NN * sizeof(int));
    cudaMemsetAsync(pcnt, 0, NN * sizeof(int));
    cudaMemsetAsync(pSeraw, 0, (size_t)NN * FEIN * sizeof(float));
    cudaMemsetAsync(out, 0, (size_t)NG * H * sizeof(float));

    // h0 = h_in @ W_embed + b_embed
    launch_gemm(ph, NN, h_in, W_embed, H, nullptr, nullptr, 0, nullptr, b_embed, 0, 0);

    // edge preprocessing: deg, S_eraw, CSR
    edge_pre<<<(NE + 255) / 256, 256>>>(e_raw, rec);
    scan1<<<40, SCB>>>();
    scan2<<<1, 32>>>(40);
    scan3<<<40, SCB>>>();
    deg2float<<<(NN + 255) / 256, 256>>>();
    csr_fill<<<(NE + 255) / 256, 256>>>(send, rec);

    // S_e0 = S_eraw @ W_eembed + deg * b_eembed
    launch_gemm(pSe0, NN, pSeraw, W_eembed, FEIN, nullptr, nullptr, 0,
                nullptr, b_eembed, 0, 1);

    float* hc = ph;
    float* hn = ph + (size_t)NN * H;
    float* Apool[2] = {pA, pA + (size_t)NN * H};
    float* Bpool[2] = {pB, pB + (size_t)NN * H};
    float* Cpool[2] = {pC, pC + H * H};
    float* bpool[2] = {pbv, pbv + H};
    const float* Ac = nullptr;
    const float* Bc = nullptr;
    const float* Cc = nullptr;   // null => identity
    const float* bc = nullptr;   // null => zero
    int flip = 0;

    for (int L = 0; L < 4; L++) {
        const float* Wm1 = Wm + (size_t)L * 384 * H;
        const float* Wm2 = Wm1 + 128 * H;
        const float* Wm3 = Wm1 + 256 * H;
        const float* bmL = bm + L * H;
        const float* Wh1 = Wh + (size_t)L * 256 * H;
        const float* Wh2 = Wh1 + 128 * H;
        const float* bhL = bh + L * H;
        const float* We1 = We + (size_t)L * 384 * H;
        const float* We2 = We1 + 128 * H;
        const float* We3 = We1 + 256 * H;
        const float* beL = be + L * H;

        // X = h@Wm1 + A~@Wm3 ; AdjX = Adj(X)
        launch_gemm(pX, NN, hc, Wm1, H, Ac, Wm3, H, nullptr, nullptr, 0, 0);
        adj_gather<<<NN / 2, 256>>>(pX, pAdj);

        // CW = C~@Wm3, bW = b~@Wm3 + bm
        const float* CWp;
        if (Cc) { small_mm<<<H, H>>>(Cc, Wm3, pCW); CWp = pCW; } else CWp = Wm3;
        const float* bWp;
        if (bc) { vecmat<<<1, H>>>(bc, Wm3, bmL, pbW); bWp = pbW; } else bWp = bmL;

        // T1 = Se0@CW + AdjX
        launch_gemm(pT1, NN, pSe0, CWp, H, nullptr, nullptr, 0, pAdj, nullptr, 0, 0);
        // agg = deg*(h@Wm2 + B~@Wm3 + bW) + T1   (into pAdj)
        launch_gemm(pAdj, NN, hc, Wm2, H, Bc, Wm3, H, pT1, bWp, 1, 1);
        // h' = h@Wh1 + agg@Wh2 + bh
        launch_gemm(hn, NN, hc, Wh1, H, pAdj, Wh2, H, nullptr, bhL, 0, 0);

        if (L < 3) {
            float* An = Apool[flip];
            float* Bn = Bpool[flip];
            launch_gemm(An, NN, hc, We1, H, Ac, We3, H, nullptr, nullptr, 0, 0);
            launch_gemm(Bn, NN, hc, We2, H, Bc, We3, H, nullptr, nullptr, 0, 0);
            const float* Cn;
            const float* bn;
            if (Cc) { small_mm<<<H, H>>>(Cc, We3, Cpool[flip]); Cn = Cpool[flip]; }
            else Cn = We3;
            if (bc) { vecmat<<<1, H>>>(bc, We3, beL, bpool[flip]); bn = bpool[flip]; }
            else bn = beL;
            Ac = An; Bc = Bn; Cc = Cn; bc = bn;
            flip ^= 1;
        }
        float* tsw = hc; hc = hn; hn = tsw;
    }

    // out[g] = sum over nodes of graph g of h_final
    pool_kernel<<<(NN * 32 + 255) / 256, 256>>>(hc, batch, out);
}